// round 11
// baseline (speedup 1.0000x reference)
#include <cuda_runtime.h>
#include <cuda.h>
#include <cuda_bf16.h>
#include <cstdint>
#include <dlfcn.h>

#define T 1024
#define H 1024
#define F 768
#define E 32
#define K 4

#define MAXTILES 64
#define PITCH 80
#define PLANE 10240
#define APAIR 20480
#define NC1 32
#define NC2 24
#define A1_TILE (NC1*APAIR)
#define ACT_TILE (NC2*APAIR)

#define OFF_MBAR 0
#define OFF_AP   1024
#define OFF_BP   (OFF_AP + 2*APAIR)
#define OFF_RAW  (OFF_BP + 2*APAIR)
#define SMEM_TOTAL (OFF_RAW + 2*16384)  /* 115712 */
#define TX_ALL (APAIR + 16384)

// ---------------- scratch ----------------
__device__ float    g_topk_w[T * K];
__device__ int      g_topk_id[T * K];
__device__ int      g_offset[E + 1];
__device__ int      g_tile_base[E];
__device__ int      g_row_of[T * K];
__device__ __align__(16) char g_A1[(size_t)MAXTILES * A1_TILE];
__device__ __align__(16) char g_act[(size_t)MAXTILES * ACT_TILE];
__device__ float    g_y[(size_t)T * K * H];

// ---------------- helpers ----------------
__device__ __forceinline__ uint32_t smem_u32(const void* p) {
    uint32_t a;
    asm("{ .reg .u64 t; cvta.to.shared.u64 t, %1; cvt.u32.u64 %0, t; }" : "=r"(a) : "l"(p));
    return a;
}

#define MBAR_INIT(a, c) \
    asm volatile("mbarrier.init.shared.b64 [%0], %1;" :: "r"((uint32_t)(a)), "r"((uint32_t)(c)) : "memory")
#define MBAR_EXPECT(a, tx) \
    asm volatile("mbarrier.arrive.expect_tx.shared.b64 _, [%0], %1;" :: "r"((uint32_t)(a)), "r"((uint32_t)(tx)) : "memory")
#define MBAR_WAIT(a, ph) do { \
    asm volatile("{\n\t.reg .pred P;\n\tWL%=:\n\t" \
        "mbarrier.try_wait.parity.acquire.cta.shared::cta.b64 P, [%0], %1, 0x989680;\n\t" \
        "@P bra.uni WD%=;\n\tbra.uni WL%=;\n\tWD%=:\n\t}" \
        :: "r"((uint32_t)(a)), "r"((uint32_t)(ph)) : "memory"); } while (0)
#define BULK_G2S(dst, src, sz, mb) \
    asm volatile("cp.async.bulk.shared::cluster.global.mbarrier::complete_tx::bytes [%0], [%1], %2, [%3];" \
        :: "r"((uint32_t)(dst)), "l"(src), "r"((uint32_t)(sz)), "r"((uint32_t)(mb)) : "memory")
#define TMA2D(dst, map, x, y, mb) \
    asm volatile("cp.async.bulk.tensor.2d.shared::cta.global.tile.mbarrier::complete_tx::bytes " \
        "[%0], [%1, {%2, %3}], [%4];" \
        :: "r"((uint32_t)(dst)), "l"(map), "r"((int)(x)), "r"((int)(y)), "r"((uint32_t)(mb)) : "memory")

#define LDM4(r, addr) \
    asm volatile("ldmatrix.sync.aligned.m8n8.x4.shared.b16 {%0,%1,%2,%3}, [%4];" \
        : "=r"((r)[0]), "=r"((r)[1]), "=r"((r)[2]), "=r"((r)[3]) : "r"(addr))

#define MMA16816(d, a, b0, b1) \
    asm volatile("mma.sync.aligned.m16n8k16.row.col.f32.bf16.bf16.f32 " \
        "{%0,%1,%2,%3}, {%4,%5,%6,%7}, {%8,%9}, {%0,%1,%2,%3};" \
        : "+f"((d)[0]), "+f"((d)[1]), "+f"((d)[2]), "+f"((d)[3]) \
        : "r"((a)[0]), "r"((a)[1]), "r"((a)[2]), "r"((a)[3]), "r"(b0), "r"(b1))

__device__ __forceinline__ void cvt_split4(float4 v, uint2& hi, uint2& lo) {
    uint32_t h01, h23, l01, l23;
    asm("cvt.rn.bf16x2.f32 %0, %1, %2;" : "=r"(h01) : "f"(v.y), "f"(v.x));
    asm("cvt.rn.bf16x2.f32 %0, %1, %2;" : "=r"(h23) : "f"(v.w), "f"(v.z));
    float h0 = __uint_as_float(h01 << 16), h1 = __uint_as_float(h01 & 0xFFFF0000u);
    float h2 = __uint_as_float(h23 << 16), h3 = __uint_as_float(h23 & 0xFFFF0000u);
    asm("cvt.rn.bf16x2.f32 %0, %1, %2;" : "=r"(l01) : "f"(v.y - h1), "f"(v.x - h0));
    asm("cvt.rn.bf16x2.f32 %0, %1, %2;" : "=r"(l23) : "f"(v.w - h3), "f"(v.z - h2));
    hi = make_uint2(h01, h23);
    lo = make_uint2(l01, l23);
}

__device__ __forceinline__ float silu(float x) { return x / (1.f + __expf(-x)); }

// ---------------- router ----------------
__global__ void router_kernel(const float* __restrict__ hs,
                              const float* __restrict__ gw) {
    int warp = (blockIdx.x * blockDim.x + threadIdx.x) >> 5;
    int lane = threadIdx.x & 31;
    if (warp >= T) return;

    const float4* x4 = (const float4*)(hs + (size_t)warp * H);
    const float4* g4 = (const float4*)(gw + (size_t)lane * H);
    float acc = 0.f;
#pragma unroll 4
    for (int i = 0; i < H / 4; i++) {
        float4 xv = x4[i];
        float4 gv = g4[i];
        acc += xv.x * gv.x + xv.y * gv.y + xv.z * gv.z + xv.w * gv.w;
    }
    float m = acc;
#pragma unroll
    for (int o = 16; o; o >>= 1) m = fmaxf(m, __shfl_xor_sync(0xffffffffu, m, o));
    float p = __expf(acc - m);
    float s = p;
#pragma unroll
    for (int o = 16; o; o >>= 1) s += __shfl_xor_sync(0xffffffffu, s, o);
    float prob = p / s;

    float cur = prob;
    float wv[K];
    int   wid[K];
#pragma unroll
    for (int k = 0; k < K; k++) {
        float v = cur;
        int who = lane;
#pragma unroll
        for (int o = 16; o; o >>= 1) {
            float ov = __shfl_xor_sync(0xffffffffu, v, o);
            int   oi = __shfl_xor_sync(0xffffffffu, who, o);
            if (ov > v || (ov == v && oi < who)) { v = ov; who = oi; }
        }
        wv[k] = v;
        wid[k] = who;
        if (lane == who) cur = -1.f;
    }
    if (lane == 0) {
        float ws = wv[0] + wv[1] + wv[2] + wv[3];
        float inv = 1.f / ws;
#pragma unroll
        for (int k = 0; k < K; k++) {
            g_topk_w[warp * K + k]  = wv[k] * inv;
            g_topk_id[warp * K + k] = wid[k];
        }
    }
}

// ---------------- bucket ----------------
__global__ void bucket_kernel() {
    __shared__ int cnt[E];
    __shared__ int curp[E];
    __shared__ int offp[E + 1];
    int t = threadIdx.x;
    if (t < E) cnt[t] = 0;
    __syncthreads();
    int ids[K];
#pragma unroll
    for (int k = 0; k < K; k++) {
        ids[k] = g_topk_id[t * K + k];
        atomicAdd(&cnt[ids[k]], 1);
    }
    __syncthreads();
    if (t == 0) {
        int a = 0, tb = 0;
        for (int e = 0; e < E; e++) {
            offp[e] = a; curp[e] = a; a += cnt[e];
            g_tile_base[e] = tb; tb += (cnt[e] + 127) >> 7;
        }
        offp[E] = a;
    }
    __syncthreads();
#pragma unroll
    for (int k = 0; k < K; k++) {
        int pos = atomicAdd(&curp[ids[k]], 1);
        g_row_of[t * K + k] = pos;
    }
    if (t <= E) g_offset[t] = offp[t];
}

// ---------------- hs -> chunked hi/lo planes ----------------
__global__ void hs_chunk_kernel(const float* __restrict__ hs) {
    int t = blockIdx.x;
    __shared__ int dtile[K], djj[K];
    if (threadIdx.x < K) {
        int r = g_row_of[t * K + threadIdx.x];
        int e = g_topk_id[t * K + threadIdx.x];
        int j = r - g_offset[e];
        dtile[threadIdx.x] = g_tile_base[e] + (j >> 7);
        djj[threadIdx.x] = j & 127;
    }
    __syncthreads();
    int u = threadIdx.x;
    int c = u >> 2, p = u & 3;
    int k0 = c * 32 + p * 8;
    float4 v0 = *(const float4*)(hs + (size_t)t * H + k0);
    float4 v1 = *(const float4*)(hs + (size_t)t * H + k0 + 4);
    uint2 h0, l0, h1, l1;
    cvt_split4(v0, h0, l0);
    cvt_split4(v1, h1, l1);
    uint4 hv = make_uint4(h0.x, h0.y, h1.x, h1.y);
    uint4 lv = make_uint4(l0.x, l0.y, l1.x, l1.y);
#pragma unroll
    for (int k = 0; k < K; k++) {
        char* base = g_A1 + (size_t)dtile[k] * A1_TILE + c * APAIR + djj[k] * PITCH + p * 16;
        *(uint4*)base = hv;
        *(uint4*)(base + PLANE) = lv;
    }
}

// ---------------- shared GEMM pieces ----------------
// converter threads ct=0..127, one B row each
__device__ __forceinline__ void convert_b(char* smem, int slot, int ct) {
    const char* rp = smem + OFF_RAW + slot * 16384 + ct * 128;
    char* hp = smem + OFF_BP + slot * APAIR + ct * PITCH;
#pragma unroll
    for (int q = 0; q < 8; q++) {
        int qq = (q + ct) & 7;
        float4 v = *(const float4*)(rp + qq * 16);
        uint2 hi, lo;
        cvt_split4(v, hi, lo);
        *(uint2*)(hp + qq * 8) = hi;
        *(uint2*)(hp + PLANE + qq * 8) = lo;
    }
}

__device__ __forceinline__ void mma_phase(uint32_t sb, int slot, int lane, int wm,
                                          const int brow[4], float acc[32][4]) {
    const uint32_t Ah = sb + OFF_AP + slot * APAIR;
    const uint32_t Bh = sb + OFF_BP + slot * APAIR;
#pragma unroll
    for (int ks = 0; ks < 2; ks++) {
        const uint32_t kb = ks * 32;
        const uint32_t lrow = (lane & 15), lcol = (lane >> 4) * 16;
        uint32_t ah[4][4], al[4][4];
#pragma unroll
        for (int i = 0; i < 4; i++) {
            uint32_t off = (uint32_t)((wm * 64 + i * 16 + lrow) * PITCH) + lcol + kb;
            LDM4(ah[i], Ah + off);
            LDM4(al[i], Ah + PLANE + off);
        }
        uint32_t bh[4][4], bl[4][4];
#pragma unroll
        for (int j2 = 0; j2 < 4; j2++) {
            uint32_t off = (uint32_t)((brow[j2] + lrow) * PITCH) + lcol + kb;
            LDM4(bh[j2], Bh + off);
            LDM4(bl[j2], Bh + PLANE + off);
        }
#pragma unroll
        for (int i = 0; i < 4; i++)
#pragma unroll
            for (int jt = 0; jt < 8; jt++) {
                int j2 = jt >> 1, hsel = jt & 1;
                MMA16816(acc[i * 8 + jt], ah[i], bh[j2][hsel], bh[j2][2 + hsel]);
            }
#pragma unroll
        for (int i = 0; i < 4; i++)
#pragma unroll
            for (int jt = 0; jt < 8; jt++) {
                int j2 = jt >> 1, hsel = jt & 1;
                MMA16816(acc[i * 8 + jt], ah[i], bl[j2][hsel], bl[j2][2 + hsel]);
            }
#pragma unroll
        for (int i = 0; i < 4; i++)
#pragma unroll
            for (int jt = 0; jt < 8; jt++) {
                int j2 = jt >> 1, hsel = jt & 1;
                MMA16816(acc[i * 8 + jt], al[i], bh[j2][hsel], bh[j2][2 + hsel]);
            }
    }
}

__device__ __forceinline__ void stage_chunk(uint32_t sb, const char* asrc, int cc,
                                            const CUtensorMap* bmap, int y0, int y1,
                                            bool split) {
    int slot = cc & 1;
    uint32_t fb = sb + OFF_MBAR + slot * 8;
    MBAR_EXPECT(fb, TX_ALL);
    BULK_G2S(sb + OFF_AP + slot * APAIR, asrc + (size_t)cc * APAIR, APAIR, fb);
    uint32_t raw = sb + OFF_RAW + slot * 16384;
    if (split) {
        TMA2D(raw, bmap, cc * 32, y0, fb);
        TMA2D(raw + 8192, bmap, cc * 32, y1, fb);
    } else {
        TMA2D(raw, bmap, cc * 32, y0, fb);
    }
}

// warp-specialized pipeline: warps 0-3 MMA only; warps 4-7 TMA wait + convert + staging
__device__ __forceinline__ void gemm_mainloop(char* smem, uint32_t sb, int tid, int lane,
                                              int wm, const int brow[4], const char* asrc,
                                              const CUtensorMap* bmap, int y0, int y1,
                                              bool split, int nc, float acc[32][4]) {
    if (tid == 0) {
        MBAR_INIT(sb + OFF_MBAR, 1);
        MBAR_INIT(sb + OFF_MBAR + 8, 1);
    }
    __syncthreads();
    if (tid == 128) {
        stage_chunk(sb, asrc, 0, bmap, y0, y1, split);
        stage_chunk(sb, asrc, 1, bmap, y0, y1, split);
    }
    if (tid >= 128) {   // converters: chunk 0
        MBAR_WAIT(sb + OFF_MBAR, 0);
        convert_b(smem, 0, tid - 128);
    }
    __syncthreads();

    for (int c = 0; c < nc; c++) {
        int slot = c & 1;
        if (tid < 128) {
            // fast-path visibility wait for AP[slot] (already completed)
            MBAR_WAIT(sb + OFF_MBAR + slot * 8, (c >> 1) & 1);
            mma_phase(sb, slot, lane, wm, brow, acc);
        } else if (c + 1 < nc) {
            int ns = (c + 1) & 1;
            MBAR_WAIT(sb + OFF_MBAR + ns * 8, ((c + 1) >> 1) & 1);
            convert_b(smem, ns, tid - 128);
        }
        __syncthreads();
        if (tid == 128 && c + 2 < nc)
            stage_chunk(sb, asrc, c + 2, bmap, y0, y1, split);
    }
}

// ================= GEMM1 =================
__global__ __launch_bounds__(256, 1) void gemm1_mma(const __grid_constant__ CUtensorMap bmap) {
    const int e  = blockIdx.y >> 3;
    const int mt = blockIdx.y & 7;
    const int rbeg = g_offset[e], rend = g_offset[e + 1];
    const int row0 = rbeg + mt * 128;
    if (row0 >= rend) return;
    const int fbase = blockIdx.x * 64;
    const int tile = g_tile_base[e] + mt;

    extern __shared__ __align__(16) char smem[];
    const uint32_t sb = smem_u32(smem);
    const int tid = threadIdx.x, lane = tid & 31;
    const int w = (tid >> 5) & 3;
    const int wm = w & 1, wn = w >> 1;

    int brow[4];
#pragma unroll
    for (int j2 = 0; j2 < 4; j2++)
        brow[j2] = (j2 < 2) ? (wn * 32 + j2 * 16) : (64 + wn * 32 + (j2 - 2) * 16);

    const char* asrc = g_A1 + (size_t)tile * A1_TILE;
    const int y0 = e * 2 * F + fbase;
    const int y1 = e * 2 * F + F + fbase;

    float acc[32][4];
#pragma unroll
    for (int i = 0; i < 32; i++)
#pragma unroll
        for (int j = 0; j < 4; j++) acc[i][j] = 0.f;

    gemm_mainloop(smem, sb, tid, lane, wm, brow, asrc, &bmap, y0, y1, true, NC1, acc);

    __syncthreads();
    char* stage = smem + OFF_AP;
    if (tid < 128) {
#pragma unroll
        for (int i = 0; i < 4; i++)
#pragma unroll
            for (int jt = 0; jt < 4; jt++) {
                float* dg = acc[i * 8 + jt];
                float* du = acc[i * 8 + jt + 4];
                int fl = wn * 32 + jt * 8 + 2 * (lane & 3);
                int cf = fl >> 5, c32 = fl & 31;
                int j1 = wm * 64 + i * 16 + (lane >> 2);
#pragma unroll
                for (int rs = 0; rs < 2; rs++) {
                    float a0 = silu(dg[rs * 2 + 0]) * du[rs * 2 + 0];
                    float a1 = silu(dg[rs * 2 + 1]) * du[rs * 2 + 1];
                    uint32_t hp, lp;
                    asm("cvt.rn.bf16x2.f32 %0, %1, %2;" : "=r"(hp) : "f"(a1), "f"(a0));
                    float hh0 = __uint_as_float(hp << 16), hh1 = __uint_as_float(hp & 0xFFFF0000u);
                    asm("cvt.rn.bf16x2.f32 %0, %1, %2;" : "=r"(lp) : "f"(a1 - hh1), "f"(a0 - hh0));
                    char* p0 = stage + cf * APAIR + (j1 + rs * 8) * PITCH + c32 * 2;
                    *(uint32_t*)p0 = hp;
                    *(uint32_t*)(p0 + PLANE) = lp;
                }
            }
    }
    __syncthreads();
    char* dst = g_act + (size_t)tile * ACT_TILE + (size_t)(fbase >> 5) * APAIR;
#pragma unroll
    for (int i = 0; i < 10; i++) {
        int idx = tid + i * 256;
        *(uint4*)(dst + (size_t)idx * 16) = *(const uint4*)(stage + idx * 16);
    }
}

// ================= GEMM2 =================
__global__ __launch_bounds__(256, 1) void gemm2_mma(const __grid_constant__ CUtensorMap bmap) {
    const int e  = blockIdx.y >> 3;
    const int mt = blockIdx.y & 7;
    const int rbeg = g_offset[e], rend = g_offset[e + 1];
    const int row0 = rbeg + mt * 128;
    if (row0 >= rend) return;
    const int hbase = blockIdx.x * 128;
    const int tile = g_tile_base[e] + mt;

    extern __shared__ __align__(16) char smem[];
    const uint32_t sb = smem_u32(smem);
    const int tid = threadIdx.x, lane = tid & 31;
    const int w = (tid >> 5) & 3;
    const int wm = w & 1, wn = w >> 1;

    int brow[4];
#pragma unroll
    for (int j2 = 0; j2 < 4; j2++) brow[j2] = wn * 64 + j2 * 16;

    const char* asrc = g_act + (size_t)tile * ACT_TILE;
    const int y0 = e * H + hbase;

    float acc[32][4];
#pragma unroll
    for (int i = 0; i < 32; i++)
#pragma unroll
        for (int j = 0; j < 4; j++) acc[i][j] = 0.f;

    gemm_mainloop(smem, sb, tid, lane, wm, brow, asrc, &bmap, y0, 0, false, NC2, acc);

    if (tid < 128) {
#pragma unroll
        for (int i = 0; i < 4; i++)
#pragma unroll
            for (int jt = 0; jt < 8; jt++) {
                float* d = acc[i * 8 + jt];
                int hcol = hbase + wn * 64 + jt * 8 + 2 * (lane & 3);
                int r1 = row0 + wm * 64 + i * 16 + (lane >> 2);
                if (r1 < rend)
                    *(float2*)(g_y + (size_t)r1 * H + hcol) = make_float2(d[0], d[1]);
                if (r1 + 8 < rend)
                    *(float2*)(g_y + (size_t)(r1 + 8) * H + hcol) = make_float2(d[2], d[3]);
            }
    }
}

// ---------------- gather ----------------
__global__ void gather_kernel(float* __restrict__ out) {
    int t = blockIdx.x;
    __shared__ float ws[K];
    __shared__ int   rs[K];
    if (threadIdx.x < K) {
        ws[threadIdx.x] = g_topk_w[t * K + threadIdx.x];
        rs[threadIdx.x] = g_row_of[t * K + threadIdx.x];
    }
    __syncthreads();
    int h = threadIdx.x * 4;
    float4 acc = make_float4(0.f, 0.f, 0.f, 0.f);
#pragma unroll
    for (int k = 0; k < K; k++) {
        float4 v = *(const float4*)(g_y + (size_t)rs[k] * H + h);
        float w = ws[k];
        acc.x += w * v.x;
        acc.y += w * v.y;
        acc.z += w * v.z;
        acc.w += w * v.w;
    }
    *(float4*)(out + (size_t)t * H + h) = acc;
}

// ---------------- host ----------------
typedef CUresult (*encode_fn_t)(CUtensorMap*, CUtensorMapDataType, cuuint32_t, void*,
                                const cuuint64_t*, const cuuint64_t*, const cuuint32_t*,
                                const cuuint32_t*, CUtensorMapInterleave, CUtensorMapSwizzle,
                                CUtensorMapL2promotion, CUtensorMapFloatOOBfill);

extern "C" void kernel_launch(void* const* d_in, const int* in_sizes, int n_in,
                              void* d_out, int out_size) {
    const float* hs = (const float*)d_in[0];
    const float* gw = (const float*)d_in[1];
    const float* w1 = (const float*)d_in[2];
    const float* w2 = (const float*)d_in[3];
    float* out = (float*)d_out;

    static encode_fn_t enc = nullptr;
    static bool attr_done = false;
    if (!attr_done) {
        cudaFuncSetAttribute(gemm1_mma, cudaFuncAttributeMaxDynamicSharedMemorySize, SMEM_TOTAL);
        cudaFuncSetAttribute(gemm2_mma, cudaFuncAttributeMaxDynamicSharedMemorySize, SMEM_TOTAL);
        void* hlib = dlopen("libcuda.so.1", RTLD_NOW | RTLD_GLOBAL);
        if (!hlib) hlib = dlopen("libcuda.so", RTLD_NOW | RTLD_GLOBAL);
        if (hlib) enc = (encode_fn_t)dlsym(hlib, "cuTensorMapEncodeTiled");
        attr_done = true;
    }

    CUtensorMap m1, m2;
    {
        cuuint64_t dims[2] = {(cuuint64_t)H, (cuuint64_t)E * 2 * F};
        cuuint64_t strides[1] = {(cuuint64_t)H * 4};
        cuuint32_t box[2] = {32, 64};
        cuuint32_t es[2] = {1, 1};
        enc(&m1, CU_TENSOR_MAP_DATA_TYPE_FLOAT32, 2, (void*)w1, dims, strides, box, es,
            CU_TENSOR_MAP_INTERLEAVE_NONE, CU_TENSOR_MAP_SWIZZLE_NONE,
            CU_TENSOR_MAP_L2_PROMOTION_L2_128B, CU_TENSOR_MAP_FLOAT_OOB_FILL_NONE);
    }
    {
        cuuint64_t dims[2] = {(cuuint64_t)F, (cuuint64_t)E * H};
        cuuint64_t strides[1] = {(cuuint64_t)F * 4};
        cuuint32_t box[2] = {32, 128};
        cuuint32_t es[2] = {1, 1};
        enc(&m2, CU_TENSOR_MAP_DATA_TYPE_FLOAT32, 2, (void*)w2, dims, strides, box, es,
            CU_TENSOR_MAP_INTERLEAVE_NONE, CU_TENSOR_MAP_SWIZZLE_NONE,
            CU_TENSOR_MAP_L2_PROMOTION_L2_128B, CU_TENSOR_MAP_FLOAT_OOB_FILL_NONE);
    }

    router_kernel<<<T / 4, 128>>>(hs, gw);
    bucket_kernel<<<1, 1024>>>();
    hs_chunk_kernel<<<T, 128>>>(hs);
    gemm1_mma<<<dim3(F / 64, E * 8), 256, SMEM_TOTAL>>>(m1);
    gemm2_mma<<<dim3(H / 128, E * 8), 256, SMEM_TOTAL>>>(m2);
    gather_kernel<<<T, 256>>>(out);
}

// round 12
// speedup vs baseline: 1.0804x; 1.0804x over previous
#include <cuda_runtime.h>
#include <cuda.h>
#include <cuda_bf16.h>
#include <cstdint>
#include <dlfcn.h>

#define T 1024
#define H 1024
#define F 768
#define E 32
#define K 4

#define MAXTILES 64
#define PITCH 80
#define PLANE 10240
#define APAIR 20480
#define NC1 32
#define NC2 24
#define A1_TILE (NC1*APAIR)
#define ACT_TILE (NC2*APAIR)

#define OFF_MBAR 0
#define OFF_AP   1024
#define OFF_BP   (OFF_AP + 2*APAIR)
#define OFF_RAW  (OFF_BP + 2*APAIR)
#define SMEM_TOTAL (OFF_RAW + 2*16384)  /* 115712 */
#define TX_ALL (APAIR + 16384)

#define NTHR 384   /* 8 MMA warps + 4 converter warps */

// ---------------- scratch ----------------
__device__ float    g_topk_w[T * K];
__device__ int      g_topk_id[T * K];
__device__ int      g_offset[E + 1];
__device__ int      g_tile_base[E];
__device__ int      g_row_of[T * K];
__device__ __align__(16) char g_A1[(size_t)MAXTILES * A1_TILE];
__device__ __align__(16) char g_act[(size_t)MAXTILES * ACT_TILE];
__device__ float    g_y[(size_t)T * K * H];

// ---------------- helpers ----------------
__device__ __forceinline__ uint32_t smem_u32(const void* p) {
    uint32_t a;
    asm("{ .reg .u64 t; cvta.to.shared.u64 t, %1; cvt.u32.u64 %0, t; }" : "=r"(a) : "l"(p));
    return a;
}

#define MBAR_INIT(a, c) \
    asm volatile("mbarrier.init.shared.b64 [%0], %1;" :: "r"((uint32_t)(a)), "r"((uint32_t)(c)) : "memory")
#define MBAR_EXPECT(a, tx) \
    asm volatile("mbarrier.arrive.expect_tx.shared.b64 _, [%0], %1;" :: "r"((uint32_t)(a)), "r"((uint32_t)(tx)) : "memory")
#define MBAR_WAIT(a, ph) do { \
    asm volatile("{\n\t.reg .pred P;\n\tWL%=:\n\t" \
        "mbarrier.try_wait.parity.acquire.cta.shared::cta.b64 P, [%0], %1, 0x989680;\n\t" \
        "@P bra.uni WD%=;\n\tbra.uni WL%=;\n\tWD%=:\n\t}" \
        :: "r"((uint32_t)(a)), "r"((uint32_t)(ph)) : "memory"); } while (0)
#define BULK_G2S(dst, src, sz, mb) \
    asm volatile("cp.async.bulk.shared::cluster.global.mbarrier::complete_tx::bytes [%0], [%1], %2, [%3];" \
        :: "r"((uint32_t)(dst)), "l"(src), "r"((uint32_t)(sz)), "r"((uint32_t)(mb)) : "memory")
#define TMA2D(dst, map, x, y, mb) \
    asm volatile("cp.async.bulk.tensor.2d.shared::cta.global.tile.mbarrier::complete_tx::bytes " \
        "[%0], [%1, {%2, %3}], [%4];" \
        :: "r"((uint32_t)(dst)), "l"(map), "r"((int)(x)), "r"((int)(y)), "r"((uint32_t)(mb)) : "memory")

#define LDM4(r, addr) \
    asm volatile("ldmatrix.sync.aligned.m8n8.x4.shared.b16 {%0,%1,%2,%3}, [%4];" \
        : "=r"((r)[0]), "=r"((r)[1]), "=r"((r)[2]), "=r"((r)[3]) : "r"(addr))

#define MMA16816(d, a, b0, b1) \
    asm volatile("mma.sync.aligned.m16n8k16.row.col.f32.bf16.bf16.f32 " \
        "{%0,%1,%2,%3}, {%4,%5,%6,%7}, {%8,%9}, {%0,%1,%2,%3};" \
        : "+f"((d)[0]), "+f"((d)[1]), "+f"((d)[2]), "+f"((d)[3]) \
        : "r"((a)[0]), "r"((a)[1]), "r"((a)[2]), "r"((a)[3]), "r"(b0), "r"(b1))

__device__ __forceinline__ void cvt_split4(float4 v, uint2& hi, uint2& lo) {
    uint32_t h01, h23, l01, l23;
    asm("cvt.rn.bf16x2.f32 %0, %1, %2;" : "=r"(h01) : "f"(v.y), "f"(v.x));
    asm("cvt.rn.bf16x2.f32 %0, %1, %2;" : "=r"(h23) : "f"(v.w), "f"(v.z));
    float h0 = __uint_as_float(h01 << 16), h1 = __uint_as_float(h01 & 0xFFFF0000u);
    float h2 = __uint_as_float(h23 << 16), h3 = __uint_as_float(h23 & 0xFFFF0000u);
    asm("cvt.rn.bf16x2.f32 %0, %1, %2;" : "=r"(l01) : "f"(v.y - h1), "f"(v.x - h0));
    asm("cvt.rn.bf16x2.f32 %0, %1, %2;" : "=r"(l23) : "f"(v.w - h3), "f"(v.z - h2));
    hi = make_uint2(h01, h23);
    lo = make_uint2(l01, l23);
}

__device__ __forceinline__ float silu(float x) { return x / (1.f + __expf(-x)); }

// ---------------- router ----------------
__global__ void router_kernel(const float* __restrict__ hs,
                              const float* __restrict__ gw) {
    int warp = (blockIdx.x * blockDim.x + threadIdx.x) >> 5;
    int lane = threadIdx.x & 31;
    if (warp >= T) return;

    const float4* x4 = (const float4*)(hs + (size_t)warp * H);
    const float4* g4 = (const float4*)(gw + (size_t)lane * H);
    float acc = 0.f;
#pragma unroll 4
    for (int i = 0; i < H / 4; i++) {
        float4 xv = x4[i];
        float4 gv = g4[i];
        acc += xv.x * gv.x + xv.y * gv.y + xv.z * gv.z + xv.w * gv.w;
    }
    float m = acc;
#pragma unroll
    for (int o = 16; o; o >>= 1) m = fmaxf(m, __shfl_xor_sync(0xffffffffu, m, o));
    float p = __expf(acc - m);
    float s = p;
#pragma unroll
    for (int o = 16; o; o >>= 1) s += __shfl_xor_sync(0xffffffffu, s, o);
    float prob = p / s;

    float cur = prob;
    float wv[K];
    int   wid[K];
#pragma unroll
    for (int k = 0; k < K; k++) {
        float v = cur;
        int who = lane;
#pragma unroll
        for (int o = 16; o; o >>= 1) {
            float ov = __shfl_xor_sync(0xffffffffu, v, o);
            int   oi = __shfl_xor_sync(0xffffffffu, who, o);
            if (ov > v || (ov == v && oi < who)) { v = ov; who = oi; }
        }
        wv[k] = v;
        wid[k] = who;
        if (lane == who) cur = -1.f;
    }
    if (lane == 0) {
        float ws = wv[0] + wv[1] + wv[2] + wv[3];
        float inv = 1.f / ws;
#pragma unroll
        for (int k = 0; k < K; k++) {
            g_topk_w[warp * K + k]  = wv[k] * inv;
            g_topk_id[warp * K + k] = wid[k];
        }
    }
}

// ---------------- bucket ----------------
__global__ void bucket_kernel() {
    __shared__ int cnt[E];
    __shared__ int curp[E];
    __shared__ int offp[E + 1];
    int t = threadIdx.x;
    if (t < E) cnt[t] = 0;
    __syncthreads();
    int ids[K];
#pragma unroll
    for (int k = 0; k < K; k++) {
        ids[k] = g_topk_id[t * K + k];
        atomicAdd(&cnt[ids[k]], 1);
    }
    __syncthreads();
    if (t == 0) {
        int a = 0, tb = 0;
        for (int e = 0; e < E; e++) {
            offp[e] = a; curp[e] = a; a += cnt[e];
            g_tile_base[e] = tb; tb += (cnt[e] + 127) >> 7;
        }
        offp[E] = a;
    }
    __syncthreads();
#pragma unroll
    for (int k = 0; k < K; k++) {
        int pos = atomicAdd(&curp[ids[k]], 1);
        g_row_of[t * K + k] = pos;
    }
    if (t <= E) g_offset[t] = offp[t];
}

// ---------------- hs -> chunked hi/lo planes ----------------
__global__ void hs_chunk_kernel(const float* __restrict__ hs) {
    int t = blockIdx.x;
    __shared__ int dtile[K], djj[K];
    if (threadIdx.x < K) {
        int r = g_row_of[t * K + threadIdx.x];
        int e = g_topk_id[t * K + threadIdx.x];
        int j = r - g_offset[e];
        dtile[threadIdx.x] = g_tile_base[e] + (j >> 7);
        djj[threadIdx.x] = j & 127;
    }
    __syncthreads();
    int u = threadIdx.x;
    int c = u >> 2, p = u & 3;
    int k0 = c * 32 + p * 8;
    float4 v0 = *(const float4*)(hs + (size_t)t * H + k0);
    float4 v1 = *(const float4*)(hs + (size_t)t * H + k0 + 4);
    uint2 h0, l0, h1, l1;
    cvt_split4(v0, h0, l0);
    cvt_split4(v1, h1, l1);
    uint4 hv = make_uint4(h0.x, h0.y, h1.x, h1.y);
    uint4 lv = make_uint4(l0.x, l0.y, l1.x, l1.y);
#pragma unroll
    for (int k = 0; k < K; k++) {
        char* base = g_A1 + (size_t)dtile[k] * A1_TILE + c * APAIR + djj[k] * PITCH + p * 16;
        *(uint4*)base = hv;
        *(uint4*)(base + PLANE) = lv;
    }
}

// ---------------- shared GEMM pieces ----------------
__device__ __forceinline__ void convert_b(char* smem, int slot, int ct) {
    const char* rp = smem + OFF_RAW + slot * 16384 + ct * 128;
    char* hp = smem + OFF_BP + slot * APAIR + ct * PITCH;
#pragma unroll
    for (int q = 0; q < 8; q++) {
        int qq = (q + ct) & 7;
        float4 v = *(const float4*)(rp + qq * 16);
        uint2 hi, lo;
        cvt_split4(v, hi, lo);
        *(uint2*)(hp + qq * 8) = hi;
        *(uint2*)(hp + PLANE + qq * 8) = lo;
    }
}

// warp tile 32 rows x 64 B-rows; wm in 0..3 selects the 32-row slice
__device__ __forceinline__ void mma_phase(uint32_t sb, int slot, int lane, int wm,
                                          const int brow[4], float acc[16][4]) {
    const uint32_t Ah = sb + OFF_AP + slot * APAIR;
    const uint32_t Bh = sb + OFF_BP + slot * APAIR;
#pragma unroll
    for (int ks = 0; ks < 2; ks++) {
        const uint32_t kb = ks * 32;
        const uint32_t lrow = (lane & 15), lcol = (lane >> 4) * 16;
        uint32_t ah[2][4], al[2][4];
#pragma unroll
        for (int i = 0; i < 2; i++) {
            uint32_t off = (uint32_t)((wm * 32 + i * 16 + lrow) * PITCH) + lcol + kb;
            LDM4(ah[i], Ah + off);
            LDM4(al[i], Ah + PLANE + off);
        }
        uint32_t bh[4][4], bl[4][4];
#pragma unroll
        for (int j2 = 0; j2 < 4; j2++) {
            uint32_t off = (uint32_t)((brow[j2] + lrow) * PITCH) + lcol + kb;
            LDM4(bh[j2], Bh + off);
            LDM4(bl[j2], Bh + PLANE + off);
        }
#pragma unroll
        for (int i = 0; i < 2; i++)
#pragma unroll
            for (int jt = 0; jt < 8; jt++) {
                int j2 = jt >> 1, hsel = jt & 1;
                MMA16816(acc[i * 8 + jt], ah[i], bh[j2][hsel], bh[j2][2 + hsel]);
            }
#pragma unroll
        for (int i = 0; i < 2; i++)
#pragma unroll
            for (int jt = 0; jt < 8; jt++) {
                int j2 = jt >> 1, hsel = jt & 1;
                MMA16816(acc[i * 8 + jt], ah[i], bl[j2][hsel], bl[j2][2 + hsel]);
            }
#pragma unroll
        for (int i = 0; i < 2; i++)
#pragma unroll
            for (int jt = 0; jt < 8; jt++) {
                int j2 = jt >> 1, hsel = jt & 1;
                MMA16816(acc[i * 8 + jt], al[i], bh[j2][hsel], bh[j2][2 + hsel]);
            }
    }
}

__device__ __forceinline__ void stage_chunk(uint32_t sb, const char* asrc, int cc,
                                            const CUtensorMap* bmap, int y0, int y1,
                                            bool split) {
    int slot = cc & 1;
    uint32_t fb = sb + OFF_MBAR + slot * 8;
    MBAR_EXPECT(fb, TX_ALL);
    BULK_G2S(sb + OFF_AP + slot * APAIR, asrc + (size_t)cc * APAIR, APAIR, fb);
    uint32_t raw = sb + OFF_RAW + slot * 16384;
    if (split) {
        TMA2D(raw, bmap, cc * 32, y0, fb);
        TMA2D(raw + 8192, bmap, cc * 32, y1, fb);
    } else {
        TMA2D(raw, bmap, cc * 32, y0, fb);
    }
}

// warps 0-7 MMA (2 per SMSP); warps 8-11 TMA wait + convert + staging
__device__ __forceinline__ void gemm_mainloop(char* smem, uint32_t sb, int tid, int lane,
                                              int wm, const int brow[4], const char* asrc,
                                              const CUtensorMap* bmap, int y0, int y1,
                                              bool split, int nc, float acc[16][4]) {
    if (tid == 0) {
        MBAR_INIT(sb + OFF_MBAR, 1);
        MBAR_INIT(sb + OFF_MBAR + 8, 1);
    }
    __syncthreads();
    if (tid == 256) {
        stage_chunk(sb, asrc, 0, bmap, y0, y1, split);
        stage_chunk(sb, asrc, 1, bmap, y0, y1, split);
    }
    if (tid >= 256) {
        MBAR_WAIT(sb + OFF_MBAR, 0);
        convert_b(smem, 0, tid - 256);
    }
    __syncthreads();

    for (int c = 0; c < nc; c++) {
        int slot = c & 1;
        if (tid < 256) {
            MBAR_WAIT(sb + OFF_MBAR + slot * 8, (c >> 1) & 1);
            mma_phase(sb, slot, lane, wm, brow, acc);
        } else if (c + 1 < nc) {
            int ns = (c + 1) & 1;
            MBAR_WAIT(sb + OFF_MBAR + ns * 8, ((c + 1) >> 1) & 1);
            convert_b(smem, ns, tid - 256);
        }
        __syncthreads();
        if (tid == 256 && c + 2 < nc)
            stage_chunk(sb, asrc, c + 2, bmap, y0, y1, split);
    }
}

// ================= GEMM1 =================
__global__ __launch_bounds__(NTHR, 1) void gemm1_mma(const __grid_constant__ CUtensorMap bmap) {
    const int e  = blockIdx.y >> 3;
    const int mt = blockIdx.y & 7;
    const int rbeg = g_offset[e], rend = g_offset[e + 1];
    const int row0 = rbeg + mt * 128;
    if (row0 >= rend) return;
    const int fbase = blockIdx.x * 64;
    const int tile = g_tile_base[e] + mt;

    extern __shared__ __align__(16) char smem[];
    const uint32_t sb = smem_u32(smem);
    const int tid = threadIdx.x, lane = tid & 31;
    const int w = (tid >> 5) & 7;
    const int wm = w & 3, wn = w >> 2;

    int brow[4];
#pragma unroll
    for (int j2 = 0; j2 < 4; j2++)
        brow[j2] = (j2 < 2) ? (wn * 32 + j2 * 16) : (64 + wn * 32 + (j2 - 2) * 16);

    const char* asrc = g_A1 + (size_t)tile * A1_TILE;
    const int y0 = e * 2 * F + fbase;
    const int y1 = e * 2 * F + F + fbase;

    float acc[16][4];
#pragma unroll
    for (int i = 0; i < 16; i++)
#pragma unroll
        for (int j = 0; j < 4; j++) acc[i][j] = 0.f;

    gemm_mainloop(smem, sb, tid, lane, wm, brow, asrc, &bmap, y0, y1, true, NC1, acc);

    __syncthreads();
    char* stage = smem + OFF_AP;
    if (tid < 256) {
#pragma unroll
        for (int i = 0; i < 2; i++)
#pragma unroll
            for (int jt = 0; jt < 4; jt++) {
                float* dg = acc[i * 8 + jt];
                float* du = acc[i * 8 + jt + 4];
                int fl = wn * 32 + jt * 8 + 2 * (lane & 3);
                int cf = fl >> 5, c32 = fl & 31;
                int j1 = wm * 32 + i * 16 + (lane >> 2);
#pragma unroll
                for (int rs = 0; rs < 2; rs++) {
                    float a0 = silu(dg[rs * 2 + 0]) * du[rs * 2 + 0];
                    float a1 = silu(dg[rs * 2 + 1]) * du[rs * 2 + 1];
                    uint32_t hp, lp;
                    asm("cvt.rn.bf16x2.f32 %0, %1, %2;" : "=r"(hp) : "f"(a1), "f"(a0));
                    float hh0 = __uint_as_float(hp << 16), hh1 = __uint_as_float(hp & 0xFFFF0000u);
                    asm("cvt.rn.bf16x2.f32 %0, %1, %2;" : "=r"(lp) : "f"(a1 - hh1), "f"(a0 - hh0));
                    char* p0 = stage + cf * APAIR + (j1 + rs * 8) * PITCH + c32 * 2;
                    *(uint32_t*)p0 = hp;
                    *(uint32_t*)(p0 + PLANE) = lp;
                }
            }
    }
    __syncthreads();
    char* dst = g_act + (size_t)tile * ACT_TILE + (size_t)(fbase >> 5) * APAIR;
#pragma unroll
    for (int i = 0; i < 7; i++) {
        int idx = tid + i * NTHR;
        if (idx < 2560)
            *(uint4*)(dst + (size_t)idx * 16) = *(const uint4*)(stage + idx * 16);
    }
}

// ================= GEMM2 =================
__global__ __launch_bounds__(NTHR, 1) void gemm2_mma(const __grid_constant__ CUtensorMap bmap) {
    const int e  = blockIdx.y >> 3;
    const int mt = blockIdx.y & 7;
    const int rbeg = g_offset[e], rend = g_offset[e + 1];
    const int row0 = rbeg + mt * 128;
    if (row0 >= rend) return;
    const int hbase = blockIdx.x * 128;
    const int tile = g_tile_base[e] + mt;

    extern __shared__ __align__(16) char smem[];
    const uint32_t sb = smem_u32(smem);
    const int tid = threadIdx.x, lane = tid & 31;
    const int w = (tid >> 5) & 7;
    const int wm = w & 3, wn = w >> 2;

    int brow[4];
#pragma unroll
    for (int j2 = 0; j2 < 4; j2++) brow[j2] = wn * 64 + j2 * 16;

    const char* asrc = g_act + (size_t)tile * ACT_TILE;
    const int y0 = e * H + hbase;

    float acc[16][4];
#pragma unroll
    for (int i = 0; i < 16; i++)
#pragma unroll
        for (int j = 0; j < 4; j++) acc[i][j] = 0.f;

    gemm_mainloop(smem, sb, tid, lane, wm, brow, asrc, &bmap, y0, 0, false, NC2, acc);

    if (tid < 256) {
#pragma unroll
        for (int i = 0; i < 2; i++)
#pragma unroll
            for (int jt = 0; jt < 8; jt++) {
                float* d = acc[i * 8 + jt];
                int hcol = hbase + wn * 64 + jt * 8 + 2 * (lane & 3);
                int r1 = row0 + wm * 32 + i * 16 + (lane >> 2);
                if (r1 < rend)
                    *(float2*)(g_y + (size_t)r1 * H + hcol) = make_float2(d[0], d[1]);
                if (r1 + 8 < rend)
                    *(float2*)(g_y + (size_t)(r1 + 8) * H + hcol) = make_float2(d[2], d[3]);
            }
    }
}

// ---------------- gather ----------------
__global__ void gather_kernel(float* __restrict__ out) {
    int t = blockIdx.x;
    __shared__ float ws[K];
    __shared__ int   rs[K];
    if (threadIdx.x < K) {
        ws[threadIdx.x] = g_topk_w[t * K + threadIdx.x];
        rs[threadIdx.x] = g_row_of[t * K + threadIdx.x];
    }
    __syncthreads();
    int h = threadIdx.x * 4;
    float4 acc = make_float4(0.f, 0.f, 0.f, 0.f);
#pragma unroll
    for (int k = 0; k < K; k++) {
        float4 v = *(const float4*)(g_y + (size_t)rs[k] * H + h);
        float w = ws[k];
        acc.x += w * v.x;
        acc.y += w * v.y;
        acc.z += w * v.z;
        acc.w += w * v.w;
    }
    *(float4*)(out + (size_t)t * H + h) = acc;
}

// ---------------- host ----------------
typedef CUresult (*encode_fn_t)(CUtensorMap*, CUtensorMapDataType, cuuint32_t, void*,
                                const cuuint64_t*, const cuuint64_t*, const cuuint32_t*,
                                const cuuint32_t*, CUtensorMapInterleave, CUtensorMapSwizzle,
                                CUtensorMapL2promotion, CUtensorMapFloatOOBfill);

extern "C" void kernel_launch(void* const* d_in, const int* in_sizes, int n_in,
                              void* d_out, int out_size) {
    const float* hs = (const float*)d_in[0];
    const float* gw = (const float*)d_in[1];
    const float* w1 = (const float*)d_in[2];
    const float* w2 = (const float*)d_in[3];
    float* out = (float*)d_out;

    static encode_fn_t enc = nullptr;
    static bool attr_done = false;
    if (!attr_done) {
        cudaFuncSetAttribute(gemm1_mma, cudaFuncAttributeMaxDynamicSharedMemorySize, SMEM_TOTAL);
        cudaFuncSetAttribute(gemm2_mma, cudaFuncAttributeMaxDynamicSharedMemorySize, SMEM_TOTAL);
        void* hlib = dlopen("libcuda.so.1", RTLD_NOW | RTLD_GLOBAL);
        if (!hlib) hlib = dlopen("libcuda.so", RTLD_NOW | RTLD_GLOBAL);
        if (hlib) enc = (encode_fn_t)dlsym(hlib, "cuTensorMapEncodeTiled");
        attr_done = true;
    }

    CUtensorMap m1, m2;
    {
        cuuint64_t dims[2] = {(cuuint64_t)H, (cuuint64_t)E * 2 * F};
        cuuint64_t strides[1] = {(cuuint64_t)H * 4};
        cuuint32_t box[2] = {32, 64};
        cuuint32_t es[2] = {1, 1};
        enc(&m1, CU_TENSOR_MAP_DATA_TYPE_FLOAT32, 2, (void*)w1, dims, strides, box, es,
            CU_TENSOR_MAP_INTERLEAVE_NONE, CU_TENSOR_MAP_SWIZZLE_NONE,
            CU_TENSOR_MAP_L2_PROMOTION_L2_128B, CU_TENSOR_MAP_FLOAT_OOB_FILL_NONE);
    }
    {
        cuuint64_t dims[2] = {(cuuint64_t)F, (cuuint64_t)E * H};
        cuuint64_t strides[1] = {(cuuint64_t)F * 4};
        cuuint32_t box[2] = {32, 128};
        cuuint32_t es[2] = {1, 1};
        enc(&m2, CU_TENSOR_MAP_DATA_TYPE_FLOAT32, 2, (void*)w2, dims, strides, box, es,
            CU_TENSOR_MAP_INTERLEAVE_NONE, CU_TENSOR_MAP_SWIZZLE_NONE,
            CU_TENSOR_MAP_L2_PROMOTION_L2_128B, CU_TENSOR_MAP_FLOAT_OOB_FILL_NONE);
    }

    router_kernel<<<T / 4, 128>>>(hs, gw);
    bucket_kernel<<<1, 1024>>>();
    hs_chunk_kernel<<<T, 128>>>(hs);
    gemm1_mma<<<dim3(F / 64, E * 8), NTHR, SMEM_TOTAL>>>(m1);
    gemm2_mma<<<dim3(H / 128, E * 8), NTHR, SMEM_TOTAL>>>(m2);
    gather_kernel<<<T, 256>>>(out);
}

// round 13
// speedup vs baseline: 1.0806x; 1.0003x over previous
#include <cuda_runtime.h>
#include <cuda.h>
#include <cuda_bf16.h>
#include <cstdint>
#include <dlfcn.h>

#define T 1024
#define H 1024
#define F 768
#define E 32
#define K 4

#define MAXTILES 64
#define PITCH 80
#define PLANE 10240
#define APAIR 20480
#define NC1 32
#define NC2 24
#define A1_TILE (NC1*APAIR)
#define ACT_TILE (NC2*APAIR)

#define NSLOT 3
#define OFF_FULL 0                       /* 3 x 8B */
#define OFF_CVT  24
#define OFF_DONE 48
#define OFF_AP   1024                    /* 3 slots */
#define OFF_BP   (OFF_AP + NSLOT*APAIR)
#define OFF_RAW  (OFF_BP + NSLOT*APAIR)
#define SMEM_TOTAL (OFF_RAW + NSLOT*16384)  /* 173056 */
#define TX_ALL (APAIR + 16384)

#define NTHR 384   /* 8 MMA warps + 4 converter warps */

// ---------------- scratch ----------------
__device__ float    g_topk_w[T * K];
__device__ int      g_topk_id[T * K];
__device__ int      g_offset[E + 1];
__device__ int      g_tile_base[E];
__device__ int      g_row_of[T * K];
__device__ __align__(16) char g_A1[(size_t)MAXTILES * A1_TILE];
__device__ __align__(16) char g_act[(size_t)MAXTILES * ACT_TILE];
__device__ float    g_y[(size_t)T * K * H];

// ---------------- helpers ----------------
__device__ __forceinline__ uint32_t smem_u32(const void* p) {
    uint32_t a;
    asm("{ .reg .u64 t; cvta.to.shared.u64 t, %1; cvt.u32.u64 %0, t; }" : "=r"(a) : "l"(p));
    return a;
}

#define MBAR_INIT(a, c) \
    asm volatile("mbarrier.init.shared.b64 [%0], %1;" :: "r"((uint32_t)(a)), "r"((uint32_t)(c)) : "memory")
#define MBAR_EXPECT(a, tx) \
    asm volatile("mbarrier.arrive.expect_tx.shared.b64 _, [%0], %1;" :: "r"((uint32_t)(a)), "r"((uint32_t)(tx)) : "memory")
#define MBAR_ARRIVE(a) \
    asm volatile("mbarrier.arrive.shared.b64 _, [%0];" :: "r"((uint32_t)(a)) : "memory")
#define MBAR_WAIT(a, ph) do { \
    asm volatile("{\n\t.reg .pred P;\n\tWL%=:\n\t" \
        "mbarrier.try_wait.parity.acquire.cta.shared::cta.b64 P, [%0], %1, 0x989680;\n\t" \
        "@P bra.uni WD%=;\n\tbra.uni WL%=;\n\tWD%=:\n\t}" \
        :: "r"((uint32_t)(a)), "r"((uint32_t)(ph)) : "memory"); } while (0)
#define BULK_G2S(dst, src, sz, mb) \
    asm volatile("cp.async.bulk.shared::cluster.global.mbarrier::complete_tx::bytes [%0], [%1], %2, [%3];" \
        :: "r"((uint32_t)(dst)), "l"(src), "r"((uint32_t)(sz)), "r"((uint32_t)(mb)) : "memory")
#define TMA2D(dst, map, x, y, mb) \
    asm volatile("cp.async.bulk.tensor.2d.shared::cta.global.tile.mbarrier::complete_tx::bytes " \
        "[%0], [%1, {%2, %3}], [%4];" \
        :: "r"((uint32_t)(dst)), "l"(map), "r"((int)(x)), "r"((int)(y)), "r"((uint32_t)(mb)) : "memory")

#define LDM4(r, addr) \
    asm volatile("ldmatrix.sync.aligned.m8n8.x4.shared.b16 {%0,%1,%2,%3}, [%4];" \
        : "=r"((r)[0]), "=r"((r)[1]), "=r"((r)[2]), "=r"((r)[3]) : "r"(addr))

#define MMA16816(d, a, b0, b1) \
    asm volatile("mma.sync.aligned.m16n8k16.row.col.f32.bf16.bf16.f32 " \
        "{%0,%1,%2,%3}, {%4,%5,%6,%7}, {%8,%9}, {%0,%1,%2,%3};" \
        : "+f"((d)[0]), "+f"((d)[1]), "+f"((d)[2]), "+f"((d)[3]) \
        : "r"((a)[0]), "r"((a)[1]), "r"((a)[2]), "r"((a)[3]), "r"(b0), "r"(b1))

__device__ __forceinline__ void cvt_split4(float4 v, uint2& hi, uint2& lo) {
    uint32_t h01, h23, l01, l23;
    asm("cvt.rn.bf16x2.f32 %0, %1, %2;" : "=r"(h01) : "f"(v.y), "f"(v.x));
    asm("cvt.rn.bf16x2.f32 %0, %1, %2;" : "=r"(h23) : "f"(v.w), "f"(v.z));
    float h0 = __uint_as_float(h01 << 16), h1 = __uint_as_float(h01 & 0xFFFF0000u);
    float h2 = __uint_as_float(h23 << 16), h3 = __uint_as_float(h23 & 0xFFFF0000u);
    asm("cvt.rn.bf16x2.f32 %0, %1, %2;" : "=r"(l01) : "f"(v.y - h1), "f"(v.x - h0));
    asm("cvt.rn.bf16x2.f32 %0, %1, %2;" : "=r"(l23) : "f"(v.w - h3), "f"(v.z - h2));
    hi = make_uint2(h01, h23);
    lo = make_uint2(l01, l23);
}

__device__ __forceinline__ float silu(float x) { return x / (1.f + __expf(-x)); }

// ---------------- router ----------------
__global__ void router_kernel(const float* __restrict__ hs,
                              const float* __restrict__ gw) {
    int warp = (blockIdx.x * blockDim.x + threadIdx.x) >> 5;
    int lane = threadIdx.x & 31;
    if (warp >= T) return;

    const float4* x4 = (const float4*)(hs + (size_t)warp * H);
    const float4* g4 = (const float4*)(gw + (size_t)lane * H);
    float acc = 0.f;
#pragma unroll 4
    for (int i = 0; i < H / 4; i++) {
        float4 xv = x4[i];
        float4 gv = g4[i];
        acc += xv.x * gv.x + xv.y * gv.y + xv.z * gv.z + xv.w * gv.w;
    }
    float m = acc;
#pragma unroll
    for (int o = 16; o; o >>= 1) m = fmaxf(m, __shfl_xor_sync(0xffffffffu, m, o));
    float p = __expf(acc - m);
    float s = p;
#pragma unroll
    for (int o = 16; o; o >>= 1) s += __shfl_xor_sync(0xffffffffu, s, o);
    float prob = p / s;

    float cur = prob;
    float wv[K];
    int   wid[K];
#pragma unroll
    for (int k = 0; k < K; k++) {
        float v = cur;
        int who = lane;
#pragma unroll
        for (int o = 16; o; o >>= 1) {
            float ov = __shfl_xor_sync(0xffffffffu, v, o);
            int   oi = __shfl_xor_sync(0xffffffffu, who, o);
            if (ov > v || (ov == v && oi < who)) { v = ov; who = oi; }
        }
        wv[k] = v;
        wid[k] = who;
        if (lane == who) cur = -1.f;
    }
    if (lane == 0) {
        float ws = wv[0] + wv[1] + wv[2] + wv[3];
        float inv = 1.f / ws;
#pragma unroll
        for (int k = 0; k < K; k++) {
            g_topk_w[warp * K + k]  = wv[k] * inv;
            g_topk_id[warp * K + k] = wid[k];
        }
    }
}

// ---------------- bucket ----------------
__global__ void bucket_kernel() {
    __shared__ int cnt[E];
    __shared__ int curp[E];
    __shared__ int offp[E + 1];
    int t = threadIdx.x;
    if (t < E) cnt[t] = 0;
    __syncthreads();
    int ids[K];
#pragma unroll
    for (int k = 0; k < K; k++) {
        ids[k] = g_topk_id[t * K + k];
        atomicAdd(&cnt[ids[k]], 1);
    }
    __syncthreads();
    if (t == 0) {
        int a = 0, tb = 0;
        for (int e = 0; e < E; e++) {
            offp[e] = a; curp[e] = a; a += cnt[e];
            g_tile_base[e] = tb; tb += (cnt[e] + 127) >> 7;
        }
        offp[E] = a;
    }
    __syncthreads();
#pragma unroll
    for (int k = 0; k < K; k++) {
        int pos = atomicAdd(&curp[ids[k]], 1);
        g_row_of[t * K + k] = pos;
    }
    if (t <= E) g_offset[t] = offp[t];
}

// ---------------- hs -> chunked hi/lo planes ----------------
__global__ void hs_chunk_kernel(const float* __restrict__ hs) {
    int t = blockIdx.x;
    __shared__ int dtile[K], djj[K];
    if (threadIdx.x < K) {
        int r = g_row_of[t * K + threadIdx.x];
        int e = g_topk_id[t * K + threadIdx.x];
        int j = r - g_offset[e];
        dtile[threadIdx.x] = g_tile_base[e] + (j >> 7);
        djj[threadIdx.x] = j & 127;
    }
    __syncthreads();
    int u = threadIdx.x;
    int c = u >> 2, p = u & 3;
    int k0 = c * 32 + p * 8;
    float4 v0 = *(const float4*)(hs + (size_t)t * H + k0);
    float4 v1 = *(const float4*)(hs + (size_t)t * H + k0 + 4);
    uint2 h0, l0, h1, l1;
    cvt_split4(v0, h0, l0);
    cvt_split4(v1, h1, l1);
    uint4 hv = make_uint4(h0.x, h0.y, h1.x, h1.y);
    uint4 lv = make_uint4(l0.x, l0.y, l1.x, l1.y);
#pragma unroll
    for (int k = 0; k < K; k++) {
        char* base = g_A1 + (size_t)dtile[k] * A1_TILE + c * APAIR + djj[k] * PITCH + p * 16;
        *(uint4*)base = hv;
        *(uint4*)(base + PLANE) = lv;
    }
}

// ---------------- shared GEMM pieces ----------------
__device__ __forceinline__ void convert_b(char* smem, int slot, int ct) {
    const char* rp = smem + OFF_RAW + slot * 16384 + ct * 128;
    char* hp = smem + OFF_BP + slot * APAIR + ct * PITCH;
#pragma unroll
    for (int q = 0; q < 8; q++) {
        int qq = (q + ct) & 7;
        float4 v = *(const float4*)(rp + qq * 16);
        uint2 hi, lo;
        cvt_split4(v, hi, lo);
        *(uint2*)(hp + qq * 8) = hi;
        *(uint2*)(hp + PLANE + qq * 8) = lo;
    }
}

// warp tile 32 rows x 64 B-rows
__device__ __forceinline__ void mma_phase(uint32_t sb, int slot, int lane, int wm,
                                          const int brow[4], float acc[16][4]) {
    const uint32_t Ah = sb + OFF_AP + slot * APAIR;
    const uint32_t Bh = sb + OFF_BP + slot * APAIR;
#pragma unroll
    for (int ks = 0; ks < 2; ks++) {
        const uint32_t kb = ks * 32;
        const uint32_t lrow = (lane & 15), lcol = (lane >> 4) * 16;
        uint32_t ah[2][4], al[2][4];
#pragma unroll
        for (int i = 0; i < 2; i++) {
            uint32_t off = (uint32_t)((wm * 32 + i * 16 + lrow) * PITCH) + lcol + kb;
            LDM4(ah[i], Ah + off);
            LDM4(al[i], Ah + PLANE + off);
        }
        uint32_t bh[4][4], bl[4][4];
#pragma unroll
        for (int j2 = 0; j2 < 4; j2++) {
            uint32_t off = (uint32_t)((brow[j2] + lrow) * PITCH) + lcol + kb;
            LDM4(bh[j2], Bh + off);
            LDM4(bl[j2], Bh + PLANE + off);
        }
#pragma unroll
        for (int i = 0; i < 2; i++)
#pragma unroll
            for (int jt = 0; jt < 8; jt++) {
                int j2 = jt >> 1, hsel = jt & 1;
                MMA16816(acc[i * 8 + jt], ah[i], bh[j2][hsel], bh[j2][2 + hsel]);
            }
#pragma unroll
        for (int i = 0; i < 2; i++)
#pragma unroll
            for (int jt = 0; jt < 8; jt++) {
                int j2 = jt >> 1, hsel = jt & 1;
                MMA16816(acc[i * 8 + jt], ah[i], bl[j2][hsel], bl[j2][2 + hsel]);
            }
#pragma unroll
        for (int i = 0; i < 2; i++)
#pragma unroll
            for (int jt = 0; jt < 8; jt++) {
                int j2 = jt >> 1, hsel = jt & 1;
                MMA16816(acc[i * 8 + jt], al[i], bh[j2][hsel], bh[j2][2 + hsel]);
            }
    }
}

__device__ __forceinline__ void stage_chunk(uint32_t sb, const char* asrc, int cc,
                                            const CUtensorMap* bmap, int y0, int y1,
                                            bool split) {
    int slot = cc % NSLOT;
    uint32_t fb = sb + OFF_FULL + slot * 8;
    MBAR_EXPECT(fb, TX_ALL);
    BULK_G2S(sb + OFF_AP + slot * APAIR, asrc + (size_t)cc * APAIR, APAIR, fb);
    uint32_t raw = sb + OFF_RAW + slot * 16384;
    if (split) {
        TMA2D(raw, bmap, cc * 32, y0, fb);
        TMA2D(raw + 8192, bmap, cc * 32, y1, fb);
    } else {
        TMA2D(raw, bmap, cc * 32, y0, fb);
    }
}

// decoupled pipeline: warps 0-7 MMA; warps 8-11 convert; tid 256 also produces.
// per slot: full (TMA tx) -> cvt (128 arrivals) -> done (256 arrivals) -> restage
__device__ __forceinline__ void gemm_mainloop(char* smem, uint32_t sb, int tid, int lane,
                                              int wm, const int brow[4], const char* asrc,
                                              const CUtensorMap* bmap, int y0, int y1,
                                              bool split, int nc, float acc[16][4]) {
    if (tid == 0) {
#pragma unroll
        for (int s = 0; s < NSLOT; s++) {
            MBAR_INIT(sb + OFF_FULL + s * 8, 1);
            MBAR_INIT(sb + OFF_CVT  + s * 8, 128);
            MBAR_INIT(sb + OFF_DONE + s * 8, 256);
        }
    }
    __syncthreads();

    if (tid < 256) {
        for (int c = 0; c < nc; c++) {
            int slot = c % NSLOT;
            int ph = (c / NSLOT) & 1;
            MBAR_WAIT(sb + OFF_CVT + slot * 8, ph);
            mma_phase(sb, slot, lane, wm, brow, acc);
            MBAR_ARRIVE(sb + OFF_DONE + slot * 8);
        }
    } else {
        int ct = tid - 256;
        if (tid == 256) {
            stage_chunk(sb, asrc, 0, bmap, y0, y1, split);
            stage_chunk(sb, asrc, 1, bmap, y0, y1, split);
            stage_chunk(sb, asrc, 2, bmap, y0, y1, split);
        }
        for (int c = 0; c < nc; c++) {
            int slot = c % NSLOT;
            int ph = (c / NSLOT) & 1;
            MBAR_WAIT(sb + OFF_FULL + slot * 8, ph);
            convert_b(smem, slot, ct);
            MBAR_ARRIVE(sb + OFF_CVT + slot * 8);
            if (tid == 256 && c >= 1 && c + 2 < nc) {
                int ds = (c - 1) % NSLOT;
                int dph = ((c - 1) / NSLOT) & 1;
                MBAR_WAIT(sb + OFF_DONE + ds * 8, dph);
                stage_chunk(sb, asrc, c + 2, bmap, y0, y1, split);
            }
        }
    }
    __syncthreads();
}

// ================= GEMM1 =================
__global__ __launch_bounds__(NTHR, 1) void gemm1_mma(const __grid_constant__ CUtensorMap bmap) {
    const int e  = blockIdx.y >> 3;
    const int mt = blockIdx.y & 7;
    const int rbeg = g_offset[e], rend = g_offset[e + 1];
    const int row0 = rbeg + mt * 128;
    if (row0 >= rend) return;
    const int fbase = blockIdx.x * 64;
    const int tile = g_tile_base[e] + mt;

    extern __shared__ __align__(16) char smem[];
    const uint32_t sb = smem_u32(smem);
    const int tid = threadIdx.x, lane = tid & 31;
    const int w = (tid >> 5) & 7;
    const int wm = w & 3, wn = w >> 2;

    int brow[4];
#pragma unroll
    for (int j2 = 0; j2 < 4; j2++)
        brow[j2] = (j2 < 2) ? (wn * 32 + j2 * 16) : (64 + wn * 32 + (j2 - 2) * 16);

    const char* asrc = g_A1 + (size_t)tile * A1_TILE;
    const int y0 = e * 2 * F + fbase;
    const int y1 = e * 2 * F + F + fbase;

    float acc[16][4];
#pragma unroll
    for (int i = 0; i < 16; i++)
#pragma unroll
        for (int j = 0; j < 4; j++) acc[i][j] = 0.f;

    gemm_mainloop(smem, sb, tid, lane, wm, brow, asrc, &bmap, y0, y1, true, NC1, acc);

    char* stage = smem + OFF_AP;
    if (tid < 256) {
#pragma unroll
        for (int i = 0; i < 2; i++)
#pragma unroll
            for (int jt = 0; jt < 4; jt++) {
                float* dg = acc[i * 8 + jt];
                float* du = acc[i * 8 + jt + 4];
                int fl = wn * 32 + jt * 8 + 2 * (lane & 3);
                int cf = fl >> 5, c32 = fl & 31;
                int j1 = wm * 32 + i * 16 + (lane >> 2);
#pragma unroll
                for (int rs = 0; rs < 2; rs++) {
                    float a0 = silu(dg[rs * 2 + 0]) * du[rs * 2 + 0];
                    float a1 = silu(dg[rs * 2 + 1]) * du[rs * 2 + 1];
                    uint32_t hp, lp;
                    asm("cvt.rn.bf16x2.f32 %0, %1, %2;" : "=r"(hp) : "f"(a1), "f"(a0));
                    float hh0 = __uint_as_float(hp << 16), hh1 = __uint_as_float(hp & 0xFFFF0000u);
                    asm("cvt.rn.bf16x2.f32 %0, %1, %2;" : "=r"(lp) : "f"(a1 - hh1), "f"(a0 - hh0));
                    char* p0 = stage + cf * APAIR + (j1 + rs * 8) * PITCH + c32 * 2;
                    *(uint32_t*)p0 = hp;
                    *(uint32_t*)(p0 + PLANE) = lp;
                }
            }
    }
    __syncthreads();
    char* dst = g_act + (size_t)tile * ACT_TILE + (size_t)(fbase >> 5) * APAIR;
#pragma unroll
    for (int i = 0; i < 7; i++) {
        int idx = tid + i * NTHR;
        if (idx < 2560)
            *(uint4*)(dst + (size_t)idx * 16) = *(const uint4*)(stage + idx * 16);
    }
}

// ================= GEMM2 =================
__global__ __launch_bounds__(NTHR, 1) void gemm2_mma(const __grid_constant__ CUtensorMap bmap) {
    const int e  = blockIdx.y >> 3;
    const int mt = blockIdx.y & 7;
    const int rbeg = g_offset[e], rend = g_offset[e + 1];
    const int row0 = rbeg + mt * 128;
    if (row0 >= rend) return;
    const int hbase = blockIdx.x * 128;
    const int tile = g_tile_base[e] + mt;

    extern __shared__ __align__(16) char smem[];
    const uint32_t sb = smem_u32(smem);
    const int tid = threadIdx.x, lane = tid & 31;
    const int w = (tid >> 5) & 7;
    const int wm = w & 3, wn = w >> 2;

    int brow[4];
#pragma unroll
    for (int j2 = 0; j2 < 4; j2++) brow[j2] = wn * 64 + j2 * 16;

    const char* asrc = g_act + (size_t)tile * ACT_TILE;
    const int y0 = e * H + hbase;

    float acc[16][4];
#pragma unroll
    for (int i = 0; i < 16; i++)
#pragma unroll
        for (int j = 0; j < 4; j++) acc[i][j] = 0.f;

    gemm_mainloop(smem, sb, tid, lane, wm, brow, asrc, &bmap, y0, 0, false, NC2, acc);

    if (tid < 256) {
#pragma unroll
        for (int i = 0; i < 2; i++)
#pragma unroll
            for (int jt = 0; jt < 8; jt++) {
                float* d = acc[i * 8 + jt];
                int hcol = hbase + wn * 64 + jt * 8 + 2 * (lane & 3);
                int r1 = row0 + wm * 32 + i * 16 + (lane >> 2);
                if (r1 < rend)
                    *(float2*)(g_y + (size_t)r1 * H + hcol) = make_float2(d[0], d[1]);
                if (r1 + 8 < rend)
                    *(float2*)(g_y + (size_t)(r1 + 8) * H + hcol) = make_float2(d[2], d[3]);
            }
    }
}

// ---------------- gather ----------------
__global__ void gather_kernel(float* __restrict__ out) {
    int t = blockIdx.x;
    __shared__ float ws[K];
    __shared__ int   rs[K];
    if (threadIdx.x < K) {
        ws[threadIdx.x] = g_topk_w[t * K + threadIdx.x];
        rs[threadIdx.x] = g_row_of[t * K + threadIdx.x];
    }
    __syncthreads();
    int h = threadIdx.x * 4;
    float4 acc = make_float4(0.f, 0.f, 0.f, 0.f);
#pragma unroll
    for (int k = 0; k < K; k++) {
        float4 v = *(const float4*)(g_y + (size_t)rs[k] * H + h);
        float w = ws[k];
        acc.x += w * v.x;
        acc.y += w * v.y;
        acc.z += w * v.z;
        acc.w += w * v.w;
    }
    *(float4*)(out + (size_t)t * H + h) = acc;
}

// ---------------- host ----------------
typedef CUresult (*encode_fn_t)(CUtensorMap*, CUtensorMapDataType, cuuint32_t, void*,
                                const cuuint64_t*, const cuuint64_t*, const cuuint32_t*,
                                const cuuint32_t*, CUtensorMapInterleave, CUtensorMapSwizzle,
                                CUtensorMapL2promotion, CUtensorMapFloatOOBfill);

extern "C" void kernel_launch(void* const* d_in, const int* in_sizes, int n_in,
                              void* d_out, int out_size) {
    const float* hs = (const float*)d_in[0];
    const float* gw = (const float*)d_in[1];
    const float* w1 = (const float*)d_in[2];
    const float* w2 = (const float*)d_in[3];
    float* out = (float*)d_out;

    static encode_fn_t enc = nullptr;
    static bool attr_done = false;
    if (!attr_done) {
        cudaFuncSetAttribute(gemm1_mma, cudaFuncAttributeMaxDynamicSharedMemorySize, SMEM_TOTAL);
        cudaFuncSetAttribute(gemm2_mma, cudaFuncAttributeMaxDynamicSharedMemorySize, SMEM_TOTAL);
        void* hlib = dlopen("libcuda.so.1", RTLD_NOW | RTLD_GLOBAL);
        if (!hlib) hlib = dlopen("libcuda.so", RTLD_NOW | RTLD_GLOBAL);
        if (hlib) enc = (encode_fn_t)dlsym(hlib, "cuTensorMapEncodeTiled");
        attr_done = true;
    }

    CUtensorMap m1, m2;
    {
        cuuint64_t dims[2] = {(cuuint64_t)H, (cuuint64_t)E * 2 * F};
        cuuint64_t strides[1] = {(cuuint64_t)H * 4};
        cuuint32_t box[2] = {32, 64};
        cuuint32_t es[2] = {1, 1};
        enc(&m1, CU_TENSOR_MAP_DATA_TYPE_FLOAT32, 2, (void*)w1, dims, strides, box, es,
            CU_TENSOR_MAP_INTERLEAVE_NONE, CU_TENSOR_MAP_SWIZZLE_NONE,
            CU_TENSOR_MAP_L2_PROMOTION_L2_128B, CU_TENSOR_MAP_FLOAT_OOB_FILL_NONE);
    }
    {
        cuuint64_t dims[2] = {(cuuint64_t)F, (cuuint64_t)E * H};
        cuuint64_t strides[1] = {(cuuint64_t)F * 4};
        cuuint32_t box[2] = {32, 128};
        cuuint32_t es[2] = {1, 1};
        enc(&m2, CU_TENSOR_MAP_DATA_TYPE_FLOAT32, 2, (void*)w2, dims, strides, box, es,
            CU_TENSOR_MAP_INTERLEAVE_NONE, CU_TENSOR_MAP_SWIZZLE_NONE,
            CU_TENSOR_MAP_L2_PROMOTION_L2_128B, CU_TENSOR_MAP_FLOAT_OOB_FILL_NONE);
    }

    router_kernel<<<T / 4, 128>>>(hs, gw);
    bucket_kernel<<<1, 1024>>>();
    hs_chunk_kernel<<<T, 128>>>(hs);
    gemm1_mma<<<dim3(F / 64, E * 8), NTHR, SMEM_TOTAL>>>(m1);
    gemm2_mma<<<dim3(H / 128, E * 8), NTHR, SMEM_TOTAL>>>(m2);
    gather_kernel<<<T, 256>>>(out);
}

// round 14
// speedup vs baseline: 1.1264x; 1.0423x over previous
#include <cuda_runtime.h>
#include <cuda.h>
#include <cuda_bf16.h>
#include <cstdint>
#include <dlfcn.h>

#define T 1024
#define H 1024
#define F 768
#define E 32
#define K 4

#define MAXTILES 64
#define PITCH 80
#define PLANE 10240
#define APAIR 20480
#define NC1 32
#define NC2 24
#define A1_TILE (NC1*APAIR)
#define ACT_TILE (NC2*APAIR)

#define OFF_MBAR 0
#define OFF_AP   1024
#define OFF_BP   (OFF_AP + 2*APAIR)
#define OFF_RAW  (OFF_BP + 2*APAIR)
#define SMEM_TOTAL (OFF_RAW + 2*16384)  /* 115712 */
#define TX_ALL (APAIR + 16384)

// ---------------- scratch ----------------
__device__ float    g_topk_w[T * K];
__device__ int      g_topk_id[T * K];
__device__ int      g_offset[E + 1];
__device__ int      g_tile_base[E];
__device__ int      g_ntiles[E];
__device__ int      g_lastsz[E];
__device__ int      g_row_of[T * K];
__device__ __align__(16) char g_A1[(size_t)MAXTILES * A1_TILE];
__device__ __align__(16) char g_act[(size_t)MAXTILES * ACT_TILE];
__device__ float    g_y[(size_t)T * K * H];

// ---------------- helpers ----------------
__device__ __forceinline__ uint32_t smem_u32(const void* p) {
    uint32_t a;
    asm("{ .reg .u64 t; cvta.to.shared.u64 t, %1; cvt.u32.u64 %0, t; }" : "=r"(a) : "l"(p));
    return a;
}

#define MBAR_INIT(a, c) \
    asm volatile("mbarrier.init.shared.b64 [%0], %1;" :: "r"((uint32_t)(a)), "r"((uint32_t)(c)) : "memory")
#define MBAR_EXPECT(a, tx) \
    asm volatile("mbarrier.arrive.expect_tx.shared.b64 _, [%0], %1;" :: "r"((uint32_t)(a)), "r"((uint32_t)(tx)) : "memory")
#define MBAR_WAIT(a, ph) do { \
    asm volatile("{\n\t.reg .pred P;\n\tWL%=:\n\t" \
        "mbarrier.try_wait.parity.acquire.cta.shared::cta.b64 P, [%0], %1, 0x989680;\n\t" \
        "@P bra.uni WD%=;\n\tbra.uni WL%=;\n\tWD%=:\n\t}" \
        :: "r"((uint32_t)(a)), "r"((uint32_t)(ph)) : "memory"); } while (0)
#define BULK_G2S(dst, src, sz, mb) \
    asm volatile("cp.async.bulk.shared::cluster.global.mbarrier::complete_tx::bytes [%0], [%1], %2, [%3];" \
        :: "r"((uint32_t)(dst)), "l"(src), "r"((uint32_t)(sz)), "r"((uint32_t)(mb)) : "memory")
#define TMA2D(dst, map, x, y, mb) \
    asm volatile("cp.async.bulk.tensor.2d.shared::cta.global.tile.mbarrier::complete_tx::bytes " \
        "[%0], [%1, {%2, %3}], [%4];" \
        :: "r"((uint32_t)(dst)), "l"(map), "r"((int)(x)), "r"((int)(y)), "r"((uint32_t)(mb)) : "memory")

#define LDM4(r, addr) \
    asm volatile("ldmatrix.sync.aligned.m8n8.x4.shared.b16 {%0,%1,%2,%3}, [%4];" \
        : "=r"((r)[0]), "=r"((r)[1]), "=r"((r)[2]), "=r"((r)[3]) : "r"(addr))

#define MMA16816(d, a, b0, b1) \
    asm volatile("mma.sync.aligned.m16n8k16.row.col.f32.bf16.bf16.f32 " \
        "{%0,%1,%2,%3}, {%4,%5,%6,%7}, {%8,%9}, {%0,%1,%2,%3};" \
        : "+f"((d)[0]), "+f"((d)[1]), "+f"((d)[2]), "+f"((d)[3]) \
        : "r"((a)[0]), "r"((a)[1]), "r"((a)[2]), "r"((a)[3]), "r"(b0), "r"(b1))

__device__ __forceinline__ void cvt_split4(float4 v, uint2& hi, uint2& lo) {
    uint32_t h01, h23, l01, l23;
    asm("cvt.rn.bf16x2.f32 %0, %1, %2;" : "=r"(h01) : "f"(v.y), "f"(v.x));
    asm("cvt.rn.bf16x2.f32 %0, %1, %2;" : "=r"(h23) : "f"(v.w), "f"(v.z));
    float h0 = __uint_as_float(h01 << 16), h1 = __uint_as_float(h01 & 0xFFFF0000u);
    float h2 = __uint_as_float(h23 << 16), h3 = __uint_as_float(h23 & 0xFFFF0000u);
    asm("cvt.rn.bf16x2.f32 %0, %1, %2;" : "=r"(l01) : "f"(v.y - h1), "f"(v.x - h0));
    asm("cvt.rn.bf16x2.f32 %0, %1, %2;" : "=r"(l23) : "f"(v.w - h3), "f"(v.z - h2));
    hi = make_uint2(h01, h23);
    lo = make_uint2(l01, l23);
}

__device__ __forceinline__ float silu(float x) { return x / (1.f + __expf(-x)); }

// ---------------- router ----------------
__global__ void router_kernel(const float* __restrict__ hs,
                              const float* __restrict__ gw) {
    int warp = (blockIdx.x * blockDim.x + threadIdx.x) >> 5;
    int lane = threadIdx.x & 31;
    if (warp >= T) return;

    const float4* x4 = (const float4*)(hs + (size_t)warp * H);
    const float4* g4 = (const float4*)(gw + (size_t)lane * H);
    float acc = 0.f;
#pragma unroll 4
    for (int i = 0; i < H / 4; i++) {
        float4 xv = x4[i];
        float4 gv = g4[i];
        acc += xv.x * gv.x + xv.y * gv.y + xv.z * gv.z + xv.w * gv.w;
    }
    float m = acc;
#pragma unroll
    for (int o = 16; o; o >>= 1) m = fmaxf(m, __shfl_xor_sync(0xffffffffu, m, o));
    float p = __expf(acc - m);
    float s = p;
#pragma unroll
    for (int o = 16; o; o >>= 1) s += __shfl_xor_sync(0xffffffffu, s, o);
    float prob = p / s;

    float cur = prob;
    float wv[K];
    int   wid[K];
#pragma unroll
    for (int k = 0; k < K; k++) {
        float v = cur;
        int who = lane;
#pragma unroll
        for (int o = 16; o; o >>= 1) {
            float ov = __shfl_xor_sync(0xffffffffu, v, o);
            int   oi = __shfl_xor_sync(0xffffffffu, who, o);
            if (ov > v || (ov == v && oi < who)) { v = ov; who = oi; }
        }
        wv[k] = v;
        wid[k] = who;
        if (lane == who) cur = -1.f;
    }
    if (lane == 0) {
        float ws = wv[0] + wv[1] + wv[2] + wv[3];
        float inv = 1.f / ws;
#pragma unroll
        for (int k = 0; k < K; k++) {
            g_topk_w[warp * K + k]  = wv[k] * inv;
            g_topk_id[warp * K + k] = wid[k];
        }
    }
}

// ---------------- bucket: counts, offsets, mixed 128/64 tile table ----------------
__global__ void bucket_kernel() {
    __shared__ int cnt[E];
    __shared__ int curp[E];
    __shared__ int offp[E + 1];
    int t = threadIdx.x;
    if (t < E) cnt[t] = 0;
    __syncthreads();
    int ids[K];
#pragma unroll
    for (int k = 0; k < K; k++) {
        ids[k] = g_topk_id[t * K + k];
        atomicAdd(&cnt[ids[k]], 1);
    }
    __syncthreads();
    if (t == 0) {
        int a = 0, tb = 0;
        for (int e = 0; e < E; e++) {
            offp[e] = a; curp[e] = a; a += cnt[e];
            int n128 = cnt[e] >> 7, rem = cnt[e] & 127;
            int nt = n128 + (rem ? 1 : 0);
            g_ntiles[e] = nt;
            g_lastsz[e] = (rem == 0) ? 128 : (rem <= 64 ? 64 : 128);
            g_tile_base[e] = tb;
            tb += nt;
        }
        offp[E] = a;
    }
    __syncthreads();
#pragma unroll
    for (int k = 0; k < K; k++) {
        int pos = atomicAdd(&curp[ids[k]], 1);
        g_row_of[t * K + k] = pos;
    }
    if (t <= E) g_offset[t] = offp[t];
}

// ---------------- hs -> chunked hi/lo planes (tile stride = 128 rows) ----------------
__global__ void hs_chunk_kernel(const float* __restrict__ hs) {
    int t = blockIdx.x;
    __shared__ int dtile[K], djj[K];
    if (threadIdx.x < K) {
        int r = g_row_of[t * K + threadIdx.x];
        int e = g_topk_id[t * K + threadIdx.x];
        int j = r - g_offset[e];
        dtile[threadIdx.x] = g_tile_base[e] + (j >> 7);
        djj[threadIdx.x] = j & 127;
    }
    __syncthreads();
    int u = threadIdx.x;
    int c = u >> 2, p = u & 3;
    int k0 = c * 32 + p * 8;
    float4 v0 = *(const float4*)(hs + (size_t)t * H + k0);
    float4 v1 = *(const float4*)(hs + (size_t)t * H + k0 + 4);
    uint2 h0, l0, h1, l1;
    cvt_split4(v0, h0, l0);
    cvt_split4(v1, h1, l1);
    uint4 hv = make_uint4(h0.x, h0.y, h1.x, h1.y);
    uint4 lv = make_uint4(l0.x, l0.y, l1.x, l1.y);
#pragma unroll
    for (int k = 0; k < K; k++) {
        char* base = g_A1 + (size_t)dtile[k] * A1_TILE + c * APAIR + djj[k] * PITCH + p * 16;
        *(uint4*)base = hv;
        *(uint4*)(base + PLANE) = lv;
    }
}

// ---------------- shared GEMM pieces ----------------
__device__ __forceinline__ void convert_b(char* smem, int slot, int tid) {
    const char* rp = smem + OFF_RAW + slot * 16384 + tid * 128;
    char* hp = smem + OFF_BP + slot * APAIR + tid * PITCH;
#pragma unroll
    for (int q = 0; q < 8; q++) {
        int qq = (q + tid) & 7;
        float4 v = *(const float4*)(rp + qq * 16);
        uint2 hi, lo;
        cvt_split4(v, hi, lo);
        *(uint2*)(hp + qq * 8) = hi;
        *(uint2*)(hp + PLANE + qq * 8) = lo;
    }
}

// warp tile 64 rows x 64 B-rows (R10 core)
__device__ __forceinline__ void mma_phase(uint32_t sb, int slot, int lane, int wm,
                                          const int brow[4], float acc[32][4]) {
    const uint32_t Ah = sb + OFF_AP + slot * APAIR;
    const uint32_t Bh = sb + OFF_BP + slot * APAIR;
#pragma unroll
    for (int ks = 0; ks < 2; ks++) {
        const uint32_t kb = ks * 32;
        const uint32_t lrow = (lane & 15), lcol = (lane >> 4) * 16;
        uint32_t ah[4][4], al[4][4];
#pragma unroll
        for (int i = 0; i < 4; i++) {
            uint32_t off = (uint32_t)((wm * 64 + i * 16 + lrow) * PITCH) + lcol + kb;
            LDM4(ah[i], Ah + off);
            LDM4(al[i], Ah + PLANE + off);
        }
        uint32_t bh[4][4], bl[4][4];
#pragma unroll
        for (int j2 = 0; j2 < 4; j2++) {
            uint32_t off = (uint32_t)((brow[j2] + lrow) * PITCH) + lcol + kb;
            LDM4(bh[j2], Bh + off);
            LDM4(bl[j2], Bh + PLANE + off);
        }
#pragma unroll
        for (int i = 0; i < 4; i++)
#pragma unroll
            for (int jt = 0; jt < 8; jt++) {
                int j2 = jt >> 1, hsel = jt & 1;
                MMA16816(acc[i * 8 + jt], ah[i], bh[j2][hsel], bh[j2][2 + hsel]);
            }
#pragma unroll
        for (int i = 0; i < 4; i++)
#pragma unroll
            for (int jt = 0; jt < 8; jt++) {
                int j2 = jt >> 1, hsel = jt & 1;
                MMA16816(acc[i * 8 + jt], ah[i], bl[j2][hsel], bl[j2][2 + hsel]);
            }
#pragma unroll
        for (int i = 0; i < 4; i++)
#pragma unroll
            for (int jt = 0; jt < 8; jt++) {
                int j2 = jt >> 1, hsel = jt & 1;
                MMA16816(acc[i * 8 + jt], al[i], bh[j2][hsel], bh[j2][2 + hsel]);
            }
    }
}

__device__ __forceinline__ void stage_chunk(uint32_t sb, const char* asrc, int cc,
                                            const CUtensorMap* bmap, int y0, int y1,
                                            bool split) {
    int slot = cc & 1;
    uint32_t fb = sb + OFF_MBAR + slot * 8;
    MBAR_EXPECT(fb, TX_ALL);
    BULK_G2S(sb + OFF_AP + slot * APAIR, asrc + (size_t)cc * APAIR, APAIR, fb);
    uint32_t raw = sb + OFF_RAW + slot * 16384;
    if (split) {
        TMA2D(raw, bmap, cc * 32, y0, fb);
        TMA2D(raw + 8192, bmap, cc * 32, y1, fb);
    } else {
        TMA2D(raw, bmap, cc * 32, y0, fb);
    }
}

// fused pipeline (R10): MMA(c) overlaps wait+convert(c+1); one sync per iter.
// active=false warps skip MMA (64-row tiles) but keep converts + syncs.
__device__ __forceinline__ void gemm_mainloop(char* smem, uint32_t sb, int tid, int lane,
                                              int wm, const int brow[4], const char* asrc,
                                              const CUtensorMap* bmap, int y0, int y1,
                                              bool split, int nc, bool active,
                                              float acc[32][4]) {
    if (tid == 0) {
        MBAR_INIT(sb + OFF_MBAR, 1);
        MBAR_INIT(sb + OFF_MBAR + 8, 1);
    }
    __syncthreads();
    if (tid == 0) {
        stage_chunk(sb, asrc, 0, bmap, y0, y1, split);
        stage_chunk(sb, asrc, 1, bmap, y0, y1, split);
    }
    MBAR_WAIT(sb + OFF_MBAR, 0);
    convert_b(smem, 0, tid);
    __syncthreads();

    for (int c = 0; c < nc; c++) {
        int slot = c & 1;
        if (active) mma_phase(sb, slot, lane, wm, brow, acc);
        if (c + 1 < nc) {
            int ns = (c + 1) & 1;
            MBAR_WAIT(sb + OFF_MBAR + ns * 8, ((c + 1) >> 1) & 1);
            convert_b(smem, ns, tid);
        }
        __syncthreads();
        if (tid == 0 && c + 2 < nc)
            stage_chunk(sb, asrc, c + 2, bmap, y0, y1, split);
    }
}

// ================= GEMM1 =================
__global__ __launch_bounds__(128, 1) void gemm1_mma(const __grid_constant__ CUtensorMap bmap) {
    const int e  = blockIdx.y >> 3;
    const int mt = blockIdx.y & 7;
    const int ntiles = g_ntiles[e];
    if (mt >= ntiles) return;
    const int rbeg = g_offset[e], rend = g_offset[e + 1];
    const int row0 = rbeg + mt * 128;
    const int msize = (mt == ntiles - 1) ? g_lastsz[e] : 128;
    const int fbase = blockIdx.x * 64;
    const int tile = g_tile_base[e] + mt;

    extern __shared__ __align__(16) char smem[];
    const uint32_t sb = smem_u32(smem);
    const int tid = threadIdx.x, lane = tid & 31;
    const int wm = (tid >> 5) & 1, wn = tid >> 6;
    const bool active = !(msize == 64 && wm == 1);

    int brow[4];
#pragma unroll
    for (int j2 = 0; j2 < 4; j2++)
        brow[j2] = (j2 < 2) ? (wn * 32 + j2 * 16) : (64 + wn * 32 + (j2 - 2) * 16);

    const char* asrc = g_A1 + (size_t)tile * A1_TILE;
    const int y0 = e * 2 * F + fbase;
    const int y1 = e * 2 * F + F + fbase;

    float acc[32][4];
#pragma unroll
    for (int i = 0; i < 32; i++)
#pragma unroll
        for (int j = 0; j < 4; j++) acc[i][j] = 0.f;

    gemm_mainloop(smem, sb, tid, lane, wm, brow, asrc, &bmap, y0, y1, true, NC1, active, acc);

    __syncthreads();
    char* stage = smem + OFF_AP;
    if (active) {
#pragma unroll
        for (int i = 0; i < 4; i++)
#pragma unroll
            for (int jt = 0; jt < 4; jt++) {
                float* dg = acc[i * 8 + jt];
                float* du = acc[i * 8 + jt + 4];
                int fl = wn * 32 + jt * 8 + 2 * (lane & 3);
                int cf = fl >> 5, c32 = fl & 31;
                int j1 = wm * 64 + i * 16 + (lane >> 2);
#pragma unroll
                for (int rs = 0; rs < 2; rs++) {
                    float a0 = silu(dg[rs * 2 + 0]) * du[rs * 2 + 0];
                    float a1 = silu(dg[rs * 2 + 1]) * du[rs * 2 + 1];
                    uint32_t hp, lp;
                    asm("cvt.rn.bf16x2.f32 %0, %1, %2;" : "=r"(hp) : "f"(a1), "f"(a0));
                    float hh0 = __uint_as_float(hp << 16), hh1 = __uint_as_float(hp & 0xFFFF0000u);
                    asm("cvt.rn.bf16x2.f32 %0, %1, %2;" : "=r"(lp) : "f"(a1 - hh1), "f"(a0 - hh0));
                    char* p0 = stage + cf * APAIR + (j1 + rs * 8) * PITCH + c32 * 2;
                    *(uint32_t*)p0 = hp;
                    *(uint32_t*)(p0 + PLANE) = lp;
                }
            }
    }
    __syncthreads();
    char* dst = g_act + (size_t)tile * ACT_TILE + (size_t)(fbase >> 5) * APAIR;
#pragma unroll
    for (int i = 0; i < 20; i++) {
        int idx = tid + i * 128;
        *(uint4*)(dst + (size_t)idx * 16) = *(const uint4*)(stage + idx * 16);
    }
}

// ================= GEMM2 =================
__global__ __launch_bounds__(128, 1) void gemm2_mma(const __grid_constant__ CUtensorMap bmap) {
    const int e  = blockIdx.y >> 3;
    const int mt = blockIdx.y & 7;
    const int ntiles = g_ntiles[e];
    if (mt >= ntiles) return;
    const int rbeg = g_offset[e], rend = g_offset[e + 1];
    const int row0 = rbeg + mt * 128;
    const int msize = (mt == ntiles - 1) ? g_lastsz[e] : 128;
    const int hbase = blockIdx.x * 128;
    const int tile = g_tile_base[e] + mt;

    extern __shared__ __align__(16) char smem[];
    const uint32_t sb = smem_u32(smem);
    const int tid = threadIdx.x, lane = tid & 31;
    const int wm = (tid >> 5) & 1, wn = tid >> 6;
    const bool active = !(msize == 64 && wm == 1);

    int brow[4];
#pragma unroll
    for (int j2 = 0; j2 < 4; j2++) brow[j2] = wn * 64 + j2 * 16;

    const char* asrc = g_act + (size_t)tile * ACT_TILE;
    const int y0 = e * H + hbase;

    float acc[32][4];
#pragma unroll
    for (int i = 0; i < 32; i++)
#pragma unroll
        for (int j = 0; j < 4; j++) acc[i][j] = 0.f;

    gemm_mainloop(smem, sb, tid, lane, wm, brow, asrc, &bmap, y0, 0, false, NC2, active, acc);

    if (active) {
#pragma unroll
        for (int i = 0; i < 4; i++)
#pragma unroll
            for (int jt = 0; jt < 8; jt++) {
                float* d = acc[i * 8 + jt];
                int hcol = hbase + wn * 64 + jt * 8 + 2 * (lane & 3);
                int r1 = row0 + wm * 64 + i * 16 + (lane >> 2);
                if (r1 < rend)
                    *(float2*)(g_y + (size_t)r1 * H + hcol) = make_float2(d[0], d[1]);
                if (r1 + 8 < rend)
                    *(float2*)(g_y + (size_t)(r1 + 8) * H + hcol) = make_float2(d[2], d[3]);
            }
    }
}

// ---------------- gather ----------------
__global__ void gather_kernel(float* __restrict__ out) {
    int t = blockIdx.x;
    __shared__ float ws[K];
    __shared__ int   rs[K];
    if (threadIdx.x < K) {
        ws[threadIdx.x] = g_topk_w[t * K + threadIdx.x];
        rs[threadIdx.x] = g_row_of[t * K + threadIdx.x];
    }
    __syncthreads();
    int h = threadIdx.x * 4;
    float4 acc = make_float4(0.f, 0.f, 0.f, 0.f);
#pragma unroll
    for (int k = 0; k < K; k++) {
        float4 v = *(const float4*)(g_y + (size_t)rs[k] * H + h);
        float w = ws[k];
        acc.x += w * v.x;
        acc.y += w * v.y;
        acc.z += w * v.z;
        acc.w += w * v.w;
    }
    *(float4*)(out + (size_t)t * H + h) = acc;
}

// ---------------- host ----------------
typedef CUresult (*encode_fn_t)(CUtensorMap*, CUtensorMapDataType, cuuint32_t, void*,
                                const cuuint64_t*, const cuuint64_t*, const cuuint32_t*,
                                const cuuint32_t*, CUtensorMapInterleave, CUtensorMapSwizzle,
                                CUtensorMapL2promotion, CUtensorMapFloatOOBfill);

extern "C" void kernel_launch(void* const* d_in, const int* in_sizes, int n_in,
                              void* d_out, int out_size) {
    const float* hs = (const float*)d_in[0];
    const float* gw = (const float*)d_in[1];
    const float* w1 = (const float*)d_in[2];
    const float* w2 = (const float*)d_in[3];
    float* out = (float*)d_out;

    static encode_fn_t enc = nullptr;
    static bool attr_done = false;
    if (!attr_done) {
        cudaFuncSetAttribute(gemm1_mma, cudaFuncAttributeMaxDynamicSharedMemorySize, SMEM_TOTAL);
        cudaFuncSetAttribute(gemm2_mma, cudaFuncAttributeMaxDynamicSharedMemorySize, SMEM_TOTAL);
        void* hlib = dlopen("libcuda.so.1", RTLD_NOW | RTLD_GLOBAL);
        if (!hlib) hlib = dlopen("libcuda.so", RTLD_NOW | RTLD_GLOBAL);
        if (hlib) enc = (encode_fn_t)dlsym(hlib, "cuTensorMapEncodeTiled");
        attr_done = true;
    }

    CUtensorMap m1, m2;
    {
        cuuint64_t dims[2] = {(cuuint64_t)H, (cuuint64_t)E * 2 * F};
        cuuint64_t strides[1] = {(cuuint64_t)H * 4};
        cuuint32_t box[2] = {32, 64};
        cuuint32_t es[2] = {1, 1};
        enc(&m1, CU_TENSOR_MAP_DATA_TYPE_FLOAT32, 2, (void*)w1, dims, strides, box, es,
            CU_TENSOR_MAP_INTERLEAVE_NONE, CU_TENSOR_MAP_SWIZZLE_NONE,
            CU_TENSOR_MAP_L2_PROMOTION_L2_128B, CU_TENSOR_MAP_FLOAT_OOB_FILL_NONE);
    }
    {
        cuuint64_t dims[2] = {(cuuint64_t)F, (cuuint64_t)E * H};
        cuuint64_t strides[1] = {(cuuint64_t)F * 4};
        cuuint32_t box[2] = {32, 128};
        cuuint32_t es[2] = {1, 1};
        enc(&m2, CU_TENSOR_MAP_DATA_TYPE_FLOAT32, 2, (void*)w2, dims, strides, box, es,
            CU_TENSOR_MAP_INTERLEAVE_NONE, CU_TENSOR_MAP_SWIZZLE_NONE,
            CU_TENSOR_MAP_L2_PROMOTION_L2_128B, CU_TENSOR_MAP_FLOAT_OOB_FILL_NONE);
    }

    router_kernel<<<T / 4, 128>>>(hs, gw);
    bucket_kernel<<<1, 1024>>>();
    hs_chunk_kernel<<<T, 128>>>(hs);
    gemm1_mma<<<dim3(F / 64, E * 8), 128, SMEM_TOTAL>>>(m1);
    gemm2_mma<<<dim3(H / 128, E * 8), 128, SMEM_TOTAL>>>(m2);
    gather_kernel<<<T, 256>>>(out);
}